// round 5
// baseline (speedup 1.0000x reference)
#include <cuda_runtime.h>
#include <cstdint>

// DialogueSNN: B=32, S=64, V=32000, E=64, H=128, T=20, beta=0.95, thr=1.0
//
// Phase 1 (snn_masks_kernel): all 1280 spike masks (128 bits per (step,b))
//   from the m1 recurrence. Decision-identical to reference (R2 evidence).
// Phase 2 (snn_seq_kernel): per-(b,v) m2 recurrence, cur2 computed exactly as
//   the reference GEMM does: one fp32 rounding per ACTIVE h, ascending h order
//   (fma(0,w,acc) is exact, so skipping inactive bits is bit-exact).
//   Warp = (one b, 32 v): mask is warp-uniform -> uniform bit loop,
//   W2 transposed in smem -> conflict-free LDS per active bit.
//   If this step's mask equals the previous step's, reuse the previous dot
//   (bit-identical; mask repetition is common under constant cur1).

#define BETA 0.95f

// masks[step][b][word], step = s*20+t, 4 x u32 words per (step,b)
__device__ unsigned g_masks[1280 * 32 * 4];

// ---------------------------------------------------------------------------
// Kernel 1: spike-mask generation (m1 path)
// 4 blocks x 1024 threads; thread = (b_local 0..7, h 0..127); lane = h%32
// ---------------------------------------------------------------------------
__global__ void __launch_bounds__(1024)
snn_masks_kernel(const int* __restrict__ x,
                 const float* __restrict__ embed,
                 const float* __restrict__ W1,
                 const float* __restrict__ b1)
{
    __shared__ float W1s[128 * 64];   // 32 KB
    __shared__ float embs[8 * 64];    // 2 KB

    const int tid = threadIdx.x;
    for (int i = tid; i < 128 * 64; i += 1024) W1s[i] = W1[i];

    const int b_local = tid >> 7;          // 0..7
    const int h       = tid & 127;         // 0..127
    const int b       = blockIdx.x * 8 + b_local;
    const float b1v   = b1[h];
    __syncthreads();

    float m1 = 0.0f;
    for (int s = 0; s < 64; ++s) {
        if (tid < 512) {
            int bl = tid >> 6, e = tid & 63;
            int tok = x[(blockIdx.x * 8 + bl) * 64 + s];
            embs[bl * 64 + e] = embed[(size_t)tok * 64 + e];
        }
        __syncthreads();

        float acc = 0.0f;
        #pragma unroll
        for (int e = 0; e < 64; ++e)
            acc = fmaf(embs[b_local * 64 + e], W1s[h * 64 + e], acc);
        const float cur1 = acc + b1v;

        #pragma unroll 1
        for (int t = 0; t < 20; ++t) {
            const float r = (m1 > 1.0f) ? 1.0f : 0.0f;   // reset from pre-update m1
            m1 = fmaf(BETA, m1, cur1) - r;
            const unsigned bal = __ballot_sync(0xffffffffu, m1 > 1.0f);
            if ((tid & 31) == 0)
                g_masks[((((s * 20 + t) * 32) + b) << 2) + (h >> 5)] = bal;
        }
        __syncthreads();
    }
}

// ---------------------------------------------------------------------------
// Kernel 2: m2 recurrence, bit-exact sequential masked sum.
// grid = (1000 v-groups, 4 b-octets), block = 256 thr = 8 warps.
// Warp w: b = blockIdx.y*8 + w (fixed per warp). Lane: v = blockIdx.x*32+lane.
// smem: W2Ts[h][v_local] (16 KB): per-active-bit load is a conflict-free
// LDS.32 (h warp-uniform, lane-consecutive addresses).
// ---------------------------------------------------------------------------
__global__ void __launch_bounds__(256)
snn_seq_kernel(const float* __restrict__ W2,
               const float* __restrict__ b2,
               float* __restrict__ out)
{
    __shared__ float W2Ts[128 * 32];   // 16 KB

    const int tid  = threadIdx.x;
    const int lane = tid & 31;
    const int w    = tid >> 5;
    const int vb   = blockIdx.x * 32;
    const int v    = vb + lane;
    const int b    = blockIdx.y * 8 + w;

    // Transpose-load the 32-row W2 tile (coalesced GMEM reads).
    for (int i = tid; i < 32 * 128; i += 256) {
        const int v_l = i >> 7;        // 0..31
        const int h   = i & 127;       // 0..127
        W2Ts[h * 32 + v_l] = W2[(size_t)(vb + v_l) * 128 + h];
    }
    __syncthreads();

    const float b2v = b2[v];
    const uint4* mp = (const uint4*)g_masks;

    float m2 = 0.0f;
    uint4 mw = __ldg(&mp[b]);   // step 0 mask (warp-uniform load)

    // previous-step mask + dot for exact reuse (init to impossible mask)
    uint4 pm = make_uint4(0xffffffffu, 0xffffffffu, 0xffffffffu, 0xffffffffu);
    float pc = 0.0f;

    #pragma unroll 1
    for (int s = 0; s < 64; ++s) {
        #pragma unroll 1
        for (int t = 0; t < 20; ++t) {
            const int step  = s * 20 + t;
            const int nstep = (step + 1 < 1280) ? (step + 1) : step;
            const uint4 mn  = __ldg(&mp[nstep * 32 + b]);   // prefetch next mask

            float c;
            if (mw.x == pm.x && mw.y == pm.y && mw.z == pm.z && mw.w == pm.w) {
                c = pc;   // identical mask -> identical (bit-exact) dot
            } else {
                // cur2: add active W2 entries, ascending h, one rounding each —
                // bit-identical to the reference's sequential fp32 fma chain.
                c = 0.0f;
                unsigned m;
                m = mw.x;
                while (m) { const int h = __ffs(m) - 1;  m &= m - 1u;
                            c += W2Ts[(h      ) * 32 + lane]; }
                m = mw.y;
                while (m) { const int h = __ffs(m) - 1;  m &= m - 1u;
                            c += W2Ts[(h + 32 ) * 32 + lane]; }
                m = mw.z;
                while (m) { const int h = __ffs(m) - 1;  m &= m - 1u;
                            c += W2Ts[(h + 64 ) * 32 + lane]; }
                m = mw.w;
                while (m) { const int h = __ffs(m) - 1;  m &= m - 1u;
                            c += W2Ts[(h + 96 ) * 32 + lane]; }
                pm = mw;
                pc = c;
            }

            const float cc = c + b2v;   // bias after the dot (b2 is zeros)

            const float r = (m2 > 1.0f) ? 1.0f : 0.0f;  // reset from pre-update m2
            m2 = fmaf(BETA, m2, cc) - r;

            mw = mn;
        }
        // after last inner step: emit spk2 for this token (coalesced 128B/warp)
        out[((size_t)(b * 64 + s)) * 32000 + v] = (m2 > 1.0f) ? 1.0f : 0.0f;
    }
}

// ---------------------------------------------------------------------------
extern "C" void kernel_launch(void* const* d_in, const int* in_sizes, int n_in,
                              void* d_out, int out_size)
{
    const int*   x     = (const int*)  d_in[0];
    const float* embed = (const float*)d_in[1];
    const float* W1    = (const float*)d_in[2];
    const float* b1    = (const float*)d_in[3];
    const float* W2    = (const float*)d_in[4];
    const float* b2    = (const float*)d_in[5];
    float* out = (float*)d_out;

    snn_masks_kernel<<<4, 1024>>>(x, embed, W1, b1);
    snn_seq_kernel<<<dim3(1000, 4), 256>>>(W2, b2, out);
}

// round 6
// speedup vs baseline: 2.3235x; 2.3235x over previous
#include <cuda_runtime.h>
#include <cstdint>

// DialogueSNN: B=32, S=64, V=32000, E=64, H=128, T=20, beta=0.95, thr=1.0
//
// Phase 1 (snn_masks_kernel): all 1280 spike masks (128 bits per (step,b))
//   from the m1 recurrence. Proven decision-identical to reference (R5: rel_err=0).
// Phase 2 (snn_seq_kernel): per-(b,v) m2 recurrence, cur2 bit-exact vs the
//   reference fma chain: one fp32 rounding per ACTIVE h, ascending h order.
//   R6: warp = (one b, 128 v) with 4 v/thread — one LDS.128 per active bit
//   feeds 4 independent FADD chains, amortizing the FFS/branch overhead 4x.

#define BETA 0.95f

// masks[step][b][word], step = s*20+t, 4 x u32 words per (step,b)
__device__ unsigned g_masks[1280 * 32 * 4];

// ---------------------------------------------------------------------------
// Kernel 1: spike-mask generation (m1 path) — UNCHANGED (bit-exact proven)
// ---------------------------------------------------------------------------
__global__ void __launch_bounds__(1024)
snn_masks_kernel(const int* __restrict__ x,
                 const float* __restrict__ embed,
                 const float* __restrict__ W1,
                 const float* __restrict__ b1)
{
    __shared__ float W1s[128 * 64];   // 32 KB
    __shared__ float embs[8 * 64];    // 2 KB

    const int tid = threadIdx.x;
    for (int i = tid; i < 128 * 64; i += 1024) W1s[i] = W1[i];

    const int b_local = tid >> 7;          // 0..7
    const int h       = tid & 127;         // 0..127
    const int b       = blockIdx.x * 8 + b_local;
    const float b1v   = b1[h];
    __syncthreads();

    float m1 = 0.0f;
    for (int s = 0; s < 64; ++s) {
        if (tid < 512) {
            int bl = tid >> 6, e = tid & 63;
            int tok = x[(blockIdx.x * 8 + bl) * 64 + s];
            embs[bl * 64 + e] = embed[(size_t)tok * 64 + e];
        }
        __syncthreads();

        float acc = 0.0f;
        #pragma unroll
        for (int e = 0; e < 64; ++e)
            acc = fmaf(embs[b_local * 64 + e], W1s[h * 64 + e], acc);
        const float cur1 = acc + b1v;

        #pragma unroll 1
        for (int t = 0; t < 20; ++t) {
            const float r = (m1 > 1.0f) ? 1.0f : 0.0f;   // reset from pre-update m1
            m1 = fmaf(BETA, m1, cur1) - r;
            const unsigned bal = __ballot_sync(0xffffffffu, m1 > 1.0f);
            if ((tid & 31) == 0)
                g_masks[((((s * 20 + t) * 32) + b) << 2) + (h >> 5)] = bal;
        }
        __syncthreads();
    }
}

// ---------------------------------------------------------------------------
// Kernel 2: m2 recurrence, bit-exact, 4 v/thread.
// grid = (250 v-tiles, 4 b-octets), block = 256 thr = 8 warps.
// Warp w: b = blockIdx.y*8 + w. Lane owns v = vb + 4*lane .. +3.
// Dynamic smem: W2Ts[h][v_local] 128x128 floats = 64 KB. Per active bit:
// one conflict-free LDS.128 (h warp-uniform, lane-consecutive 16B chunks).
// ---------------------------------------------------------------------------
extern __shared__ float W2Ts[];   // 128*128 floats = 64 KB

__global__ void __launch_bounds__(256)
snn_seq_kernel(const float* __restrict__ W2,
               const float* __restrict__ b2,
               float* __restrict__ out)
{
    const int tid  = threadIdx.x;
    const int lane = tid & 31;
    const int w    = tid >> 5;
    const int vb   = blockIdx.x * 128;
    const int b    = blockIdx.y * 8 + w;

    // Transpose-load the 128-row W2 tile (coalesced GMEM reads; one-time STS
    // conflicts are acceptable).
    for (int i = tid; i < 128 * 128; i += 256) {
        const int v_l = i >> 7;        // 0..127
        const int h   = i & 127;       // 0..127
        W2Ts[h * 128 + v_l] = W2[(size_t)(vb + v_l) * 128 + h];
    }
    __syncthreads();

    const float4 bias = *(const float4*)(b2 + vb + 4 * lane);
    const uint4* mp = (const uint4*)g_masks;

    // this lane's float4 column base; word j adds j*1024 float4s (h' = 32j+h)
    const float4* p0 = (const float4*)W2Ts + lane;

    float4 m2 = make_float4(0.0f, 0.0f, 0.0f, 0.0f);
    uint4 mw = __ldg(&mp[b]);   // step 0 mask (warp-uniform)

    // previous-step mask + dot for exact reuse (init to impossible mask)
    uint4 pm = make_uint4(0xffffffffu, 0xffffffffu, 0xffffffffu, 0xffffffffu);
    float4 pc = make_float4(0.0f, 0.0f, 0.0f, 0.0f);

    #pragma unroll 1
    for (int s = 0; s < 64; ++s) {
        #pragma unroll 1
        for (int t = 0; t < 20; ++t) {
            const int step  = s * 20 + t;
            const int nstep = (step + 1 < 1280) ? (step + 1) : step;
            const uint4 mn  = __ldg(&mp[nstep * 32 + b]);   // prefetch next mask

            float4 c;
            if (mw.x == pm.x && mw.y == pm.y && mw.z == pm.z && mw.w == pm.w) {
                c = pc;   // identical mask -> identical (bit-exact) dot
            } else {
                // ascending h, one rounding per active bit per v — bit-exact.
                c = make_float4(0.0f, 0.0f, 0.0f, 0.0f);
                unsigned m;

                m = mw.x;
                while (m) { const int h = __ffs(m) - 1;  m &= m - 1u;
                            const float4 e = p0[(h << 5)];
                            c.x += e.x; c.y += e.y; c.z += e.z; c.w += e.w; }
                m = mw.y;
                while (m) { const int h = __ffs(m) - 1;  m &= m - 1u;
                            const float4 e = p0[1024 + (h << 5)];
                            c.x += e.x; c.y += e.y; c.z += e.z; c.w += e.w; }
                m = mw.z;
                while (m) { const int h = __ffs(m) - 1;  m &= m - 1u;
                            const float4 e = p0[2048 + (h << 5)];
                            c.x += e.x; c.y += e.y; c.z += e.z; c.w += e.w; }
                m = mw.w;
                while (m) { const int h = __ffs(m) - 1;  m &= m - 1u;
                            const float4 e = p0[3072 + (h << 5)];
                            c.x += e.x; c.y += e.y; c.z += e.z; c.w += e.w; }
                pm = mw;
                pc = c;
            }

            // bias after the dot (b2 is zeros; exact either way)
            const float cx = c.x + bias.x, cy = c.y + bias.y;
            const float cz = c.z + bias.z, cw = c.w + bias.w;

            // m2 update: reset from pre-update m2, then leaky integrate
            const float rx = (m2.x > 1.0f) ? 1.0f : 0.0f;
            const float ry = (m2.y > 1.0f) ? 1.0f : 0.0f;
            const float rz = (m2.z > 1.0f) ? 1.0f : 0.0f;
            const float rw = (m2.w > 1.0f) ? 1.0f : 0.0f;
            m2.x = fmaf(BETA, m2.x, cx) - rx;
            m2.y = fmaf(BETA, m2.y, cy) - ry;
            m2.z = fmaf(BETA, m2.z, cz) - rz;
            m2.w = fmaf(BETA, m2.w, cw) - rw;

            mw = mn;
        }
        // emit spk2 for this token (coalesced 512B/warp, 16B-aligned)
        float4 o;
        o.x = (m2.x > 1.0f) ? 1.0f : 0.0f;
        o.y = (m2.y > 1.0f) ? 1.0f : 0.0f;
        o.z = (m2.z > 1.0f) ? 1.0f : 0.0f;
        o.w = (m2.w > 1.0f) ? 1.0f : 0.0f;
        *(float4*)(out + ((size_t)(b * 64 + s)) * 32000 + vb + 4 * lane) = o;
    }
}

// ---------------------------------------------------------------------------
extern "C" void kernel_launch(void* const* d_in, const int* in_sizes, int n_in,
                              void* d_out, int out_size)
{
    const int*   x     = (const int*)  d_in[0];
    const float* embed = (const float*)d_in[1];
    const float* W1    = (const float*)d_in[2];
    const float* b1    = (const float*)d_in[3];
    const float* W2    = (const float*)d_in[4];
    const float* b2    = (const float*)d_in[5];
    float* out = (float*)d_out;

    // 64 KB dynamic smem for the weight tile (idempotent host call, capture-safe)
    cudaFuncSetAttribute(snn_seq_kernel,
                         cudaFuncAttributeMaxDynamicSharedMemorySize, 65536);

    snn_masks_kernel<<<4, 1024>>>(x, embed, W1, b1);
    snn_seq_kernel<<<dim3(250, 4), 256, 65536>>>(W2, b2, out);
}

// round 7
// speedup vs baseline: 2.7130x; 1.1676x over previous
#include <cuda_runtime.h>
#include <cstdint>

// DialogueSNN: B=32, S=64, V=32000, E=64, H=128, T=20, beta=0.95, thr=1.0
//
// Phase 1 (snn_masks_kernel): all 1280 spike masks (128 bits per (step,b))
//   from the m1 recurrence. Proven bit-exact vs reference (R5/R6: rel_err=0).
// Phase 2 (snn_seq_kernel): per-(b,v) m2 recurrence, cur2 bit-exact vs the
//   reference fma chain: one fp32 rounding per ACTIVE h, ascending h order.
//   Warp = (one b, 128 v), 4 v/thread, one LDS.128 per active bit.
//   R7: 512-thread blocks (16 warps = 2 b-octets) share one 64 KB weight
//   tile -> 48 warps/SM (was 24), closing the latency-hiding gap.

#define BETA 0.95f

// masks[step][b][word], step = s*20+t, 4 x u32 words per (step,b)
__device__ unsigned g_masks[1280 * 32 * 4];

// ---------------------------------------------------------------------------
// Kernel 1: spike-mask generation (m1 path) — UNCHANGED (bit-exact proven)
// ---------------------------------------------------------------------------
__global__ void __launch_bounds__(1024)
snn_masks_kernel(const int* __restrict__ x,
                 const float* __restrict__ embed,
                 const float* __restrict__ W1,
                 const float* __restrict__ b1)
{
    __shared__ float W1s[128 * 64];   // 32 KB
    __shared__ float embs[8 * 64];    // 2 KB

    const int tid = threadIdx.x;
    for (int i = tid; i < 128 * 64; i += 1024) W1s[i] = W1[i];

    const int b_local = tid >> 7;          // 0..7
    const int h       = tid & 127;         // 0..127
    const int b       = blockIdx.x * 8 + b_local;
    const float b1v   = b1[h];
    __syncthreads();

    float m1 = 0.0f;
    for (int s = 0; s < 64; ++s) {
        if (tid < 512) {
            int bl = tid >> 6, e = tid & 63;
            int tok = x[(blockIdx.x * 8 + bl) * 64 + s];
            embs[bl * 64 + e] = embed[(size_t)tok * 64 + e];
        }
        __syncthreads();

        float acc = 0.0f;
        #pragma unroll
        for (int e = 0; e < 64; ++e)
            acc = fmaf(embs[b_local * 64 + e], W1s[h * 64 + e], acc);
        const float cur1 = acc + b1v;

        #pragma unroll 1
        for (int t = 0; t < 20; ++t) {
            const float r = (m1 > 1.0f) ? 1.0f : 0.0f;   // reset from pre-update m1
            m1 = fmaf(BETA, m1, cur1) - r;
            const unsigned bal = __ballot_sync(0xffffffffu, m1 > 1.0f);
            if ((tid & 31) == 0)
                g_masks[((((s * 20 + t) * 32) + b) << 2) + (h >> 5)] = bal;
        }
        __syncthreads();
    }
}

// ---------------------------------------------------------------------------
// Kernel 2: m2 recurrence, bit-exact, 4 v/thread.
// grid = (250 v-tiles, 2 b-sixteens), block = 512 thr = 16 warps.
// Warp w: b = blockIdx.y*16 + w. Lane owns v = vb + 4*lane .. +3.
// Dynamic smem: W2Ts[h][v_local] 128x128 floats = 64 KB, shared by 16 warps.
// Per active bit: one conflict-free LDS.128 (h warp-uniform).
// ---------------------------------------------------------------------------
extern __shared__ float W2Ts[];   // 128*128 floats = 64 KB

__global__ void __launch_bounds__(512, 3)
snn_seq_kernel(const float* __restrict__ W2,
               const float* __restrict__ b2,
               float* __restrict__ out)
{
    const int tid  = threadIdx.x;
    const int lane = tid & 31;
    const int w    = tid >> 5;               // 0..15
    const int vb   = blockIdx.x * 128;
    const int b    = blockIdx.y * 16 + w;

    // Transpose-load the 128-row W2 tile (coalesced GMEM reads).
    for (int i = tid; i < 128 * 128; i += 512) {
        const int v_l = i >> 7;        // 0..127
        const int h   = i & 127;       // 0..127
        W2Ts[h * 128 + v_l] = W2[(size_t)(vb + v_l) * 128 + h];
    }
    __syncthreads();

    const float4 bias = *(const float4*)(b2 + vb + 4 * lane);
    const uint4* mp = (const uint4*)g_masks;

    // this lane's float4 column base; word j adds j*1024 float4s (h' = 32j+h)
    const float4* p0 = (const float4*)W2Ts + lane;

    float4 m2 = make_float4(0.0f, 0.0f, 0.0f, 0.0f);
    uint4 mw = __ldg(&mp[b]);   // step 0 mask (warp-uniform)

    // previous-step mask + dot for exact reuse (init to impossible mask)
    uint4 pm = make_uint4(0xffffffffu, 0xffffffffu, 0xffffffffu, 0xffffffffu);
    float4 pc = make_float4(0.0f, 0.0f, 0.0f, 0.0f);

    #pragma unroll 1
    for (int s = 0; s < 64; ++s) {
        #pragma unroll 1
        for (int t = 0; t < 20; ++t) {
            const int step  = s * 20 + t;
            const int nstep = (step + 1 < 1280) ? (step + 1) : step;
            const uint4 mn  = __ldg(&mp[nstep * 32 + b]);   // prefetch next mask

            float4 c;
            if (mw.x == pm.x && mw.y == pm.y && mw.z == pm.z && mw.w == pm.w) {
                c = pc;   // identical mask -> identical (bit-exact) dot
            } else {
                // ascending h, one rounding per active bit per v — bit-exact.
                c = make_float4(0.0f, 0.0f, 0.0f, 0.0f);
                unsigned m;

                m = mw.x;
                while (m) { const int h = __ffs(m) - 1;  m &= m - 1u;
                            const float4 e = p0[(h << 5)];
                            c.x += e.x; c.y += e.y; c.z += e.z; c.w += e.w; }
                m = mw.y;
                while (m) { const int h = __ffs(m) - 1;  m &= m - 1u;
                            const float4 e = p0[1024 + (h << 5)];
                            c.x += e.x; c.y += e.y; c.z += e.z; c.w += e.w; }
                m = mw.z;
                while (m) { const int h = __ffs(m) - 1;  m &= m - 1u;
                            const float4 e = p0[2048 + (h << 5)];
                            c.x += e.x; c.y += e.y; c.z += e.z; c.w += e.w; }
                m = mw.w;
                while (m) { const int h = __ffs(m) - 1;  m &= m - 1u;
                            const float4 e = p0[3072 + (h << 5)];
                            c.x += e.x; c.y += e.y; c.z += e.z; c.w += e.w; }
                pm = mw;
                pc = c;
            }

            // bias after the dot (b2 is zeros; exact either way)
            const float cx = c.x + bias.x, cy = c.y + bias.y;
            const float cz = c.z + bias.z, cw = c.w + bias.w;

            // m2 update: reset from pre-update m2, then leaky integrate
            const float rx = (m2.x > 1.0f) ? 1.0f : 0.0f;
            const float ry = (m2.y > 1.0f) ? 1.0f : 0.0f;
            const float rz = (m2.z > 1.0f) ? 1.0f : 0.0f;
            const float rw = (m2.w > 1.0f) ? 1.0f : 0.0f;
            m2.x = fmaf(BETA, m2.x, cx) - rx;
            m2.y = fmaf(BETA, m2.y, cy) - ry;
            m2.z = fmaf(BETA, m2.z, cz) - rz;
            m2.w = fmaf(BETA, m2.w, cw) - rw;

            mw = mn;
        }
        // emit spk2 for this token (coalesced 512B/warp, 16B-aligned)
        float4 o;
        o.x = (m2.x > 1.0f) ? 1.0f : 0.0f;
        o.y = (m2.y > 1.0f) ? 1.0f : 0.0f;
        o.z = (m2.z > 1.0f) ? 1.0f : 0.0f;
        o.w = (m2.w > 1.0f) ? 1.0f : 0.0f;
        *(float4*)(out + ((size_t)(b * 64 + s)) * 32000 + vb + 4 * lane) = o;
    }
}

// ---------------------------------------------------------------------------
extern "C" void kernel_launch(void* const* d_in, const int* in_sizes, int n_in,
                              void* d_out, int out_size)
{
    const int*   x     = (const int*)  d_in[0];
    const float* embed = (const float*)d_in[1];
    const float* W1    = (const float*)d_in[2];
    const float* b1    = (const float*)d_in[3];
    const float* W2    = (const float*)d_in[4];
    const float* b2    = (const float*)d_in[5];
    float* out = (float*)d_out;

    // 64 KB dynamic smem for the weight tile (idempotent host call, capture-safe)
    cudaFuncSetAttribute(snn_seq_kernel,
                         cudaFuncAttributeMaxDynamicSharedMemorySize, 65536);

    snn_masks_kernel<<<4, 1024>>>(x, embed, W1, b1);
    snn_seq_kernel<<<dim3(250, 2), 512, 65536>>>(W2, b2, out);
}

// round 8
// speedup vs baseline: 2.7767x; 1.0235x over previous
#include <cuda_runtime.h>
#include <cstdint>

// DialogueSNN: B=32, S=64, V=32000, E=64, H=128, T=20, beta=0.95, thr=1.0
//
// Phase 1 (snn_masks_kernel): all 1280 spike masks (128 bits per (step,b))
//   from the m1 recurrence. Proven bit-exact vs reference (rel_err=0).
// Phase 2 (snn_seq_kernel): per-(b,v) m2 recurrence, cur2 bit-exact vs the
//   reference fma chain: one fp32 rounding per ACTIVE h, ascending h order.
//   Warp = (one b, 128 v), 4 v/thread, one LDS.128 per active bit.
//   R8: 1024-thread blocks (32 warps = all 32 b) share one 64 KB tile,
//   2 CTA/SM -> 64 warps/SM; grid 250 = single resident wave. Mask cache
//   removed (joint-mask repetition ~never occurs; frees regs for the
//   32-reg/2-CTA occupancy target).

#define BETA 0.95f

// masks[step][b][word], step = s*20+t, 4 x u32 words per (step,b)
__device__ unsigned g_masks[1280 * 32 * 4];

// ---------------------------------------------------------------------------
// Kernel 1: spike-mask generation (m1 path) — UNCHANGED (bit-exact proven)
// ---------------------------------------------------------------------------
__global__ void __launch_bounds__(1024)
snn_masks_kernel(const int* __restrict__ x,
                 const float* __restrict__ embed,
                 const float* __restrict__ W1,
                 const float* __restrict__ b1)
{
    __shared__ float W1s[128 * 64];   // 32 KB
    __shared__ float embs[8 * 64];    // 2 KB

    const int tid = threadIdx.x;
    for (int i = tid; i < 128 * 64; i += 1024) W1s[i] = W1[i];

    const int b_local = tid >> 7;          // 0..7
    const int h       = tid & 127;         // 0..127
    const int b       = blockIdx.x * 8 + b_local;
    const float b1v   = b1[h];
    __syncthreads();

    float m1 = 0.0f;
    for (int s = 0; s < 64; ++s) {
        if (tid < 512) {
            int bl = tid >> 6, e = tid & 63;
            int tok = x[(blockIdx.x * 8 + bl) * 64 + s];
            embs[bl * 64 + e] = embed[(size_t)tok * 64 + e];
        }
        __syncthreads();

        float acc = 0.0f;
        #pragma unroll
        for (int e = 0; e < 64; ++e)
            acc = fmaf(embs[b_local * 64 + e], W1s[h * 64 + e], acc);
        const float cur1 = acc + b1v;

        #pragma unroll 1
        for (int t = 0; t < 20; ++t) {
            const float r = (m1 > 1.0f) ? 1.0f : 0.0f;   // reset from pre-update m1
            m1 = fmaf(BETA, m1, cur1) - r;
            const unsigned bal = __ballot_sync(0xffffffffu, m1 > 1.0f);
            if ((tid & 31) == 0)
                g_masks[((((s * 20 + t) * 32) + b) << 2) + (h >> 5)] = bal;
        }
        __syncthreads();
    }
}

// ---------------------------------------------------------------------------
// Kernel 2: m2 recurrence, bit-exact, 4 v/thread.
// grid = 250 v-tiles, block = 1024 thr = 32 warps = all 32 b.
// Warp w: b = w. Lane owns v = vb + 4*lane .. +3.
// Dynamic smem: W2Ts[h][v_local] 128x128 floats = 64 KB, shared by 32 warps.
// Per active bit: one conflict-free LDS.128 (h warp-uniform).
// ---------------------------------------------------------------------------
extern __shared__ float W2Ts[];   // 128*128 floats = 64 KB

__global__ void __launch_bounds__(1024, 2)
snn_seq_kernel(const float* __restrict__ W2,
               const float* __restrict__ b2,
               float* __restrict__ out)
{
    const int tid  = threadIdx.x;
    const int lane = tid & 31;
    const int b    = tid >> 5;               // warp id == batch index 0..31
    const int vb   = blockIdx.x * 128;

    // Transpose-load the 128-row W2 tile (coalesced GMEM reads).
    for (int i = tid; i < 128 * 128; i += 1024) {
        const int v_l = i >> 7;        // 0..127
        const int h   = i & 127;       // 0..127
        W2Ts[h * 128 + v_l] = W2[(size_t)(vb + v_l) * 128 + h];
    }
    __syncthreads();

    const float4 bias = *(const float4*)(b2 + vb + 4 * lane);
    const uint4* mp = (const uint4*)g_masks;

    // this lane's float4 column base; word j adds j*1024 float4s (h' = 32j+h)
    const float4* p0 = (const float4*)W2Ts + lane;

    float4 m2 = make_float4(0.0f, 0.0f, 0.0f, 0.0f);
    uint4 mw = __ldg(&mp[b]);   // step 0 mask (warp-uniform)

    #pragma unroll 1
    for (int s = 0; s < 64; ++s) {
        #pragma unroll 1
        for (int t = 0; t < 20; ++t) {
            const int step  = s * 20 + t;
            const int nstep = (step + 1 < 1280) ? (step + 1) : step;
            const uint4 mn  = __ldg(&mp[nstep * 32 + b]);   // prefetch next mask

            // ascending h, one rounding per active bit per v — bit-exact.
            float4 c = make_float4(0.0f, 0.0f, 0.0f, 0.0f);
            unsigned m;

            m = mw.x;
            while (m) { const int h = __ffs(m) - 1;  m &= m - 1u;
                        const float4 e = p0[(h << 5)];
                        c.x += e.x; c.y += e.y; c.z += e.z; c.w += e.w; }
            m = mw.y;
            while (m) { const int h = __ffs(m) - 1;  m &= m - 1u;
                        const float4 e = p0[1024 + (h << 5)];
                        c.x += e.x; c.y += e.y; c.z += e.z; c.w += e.w; }
            m = mw.z;
            while (m) { const int h = __ffs(m) - 1;  m &= m - 1u;
                        const float4 e = p0[2048 + (h << 5)];
                        c.x += e.x; c.y += e.y; c.z += e.z; c.w += e.w; }
            m = mw.w;
            while (m) { const int h = __ffs(m) - 1;  m &= m - 1u;
                        const float4 e = p0[3072 + (h << 5)];
                        c.x += e.x; c.y += e.y; c.z += e.z; c.w += e.w; }

            // bias after the dot (matches reference GEMM+bias order)
            const float cx = c.x + bias.x, cy = c.y + bias.y;
            const float cz = c.z + bias.z, cw = c.w + bias.w;

            // m2 update: reset from pre-update m2, then leaky integrate
            const float rx = (m2.x > 1.0f) ? 1.0f : 0.0f;
            const float ry = (m2.y > 1.0f) ? 1.0f : 0.0f;
            const float rz = (m2.z > 1.0f) ? 1.0f : 0.0f;
            const float rw = (m2.w > 1.0f) ? 1.0f : 0.0f;
            m2.x = fmaf(BETA, m2.x, cx) - rx;
            m2.y = fmaf(BETA, m2.y, cy) - ry;
            m2.z = fmaf(BETA, m2.z, cz) - rz;
            m2.w = fmaf(BETA, m2.w, cw) - rw;

            mw = mn;
        }
        // emit spk2 for this token (coalesced 512B/warp, 16B-aligned)
        float4 o;
        o.x = (m2.x > 1.0f) ? 1.0f : 0.0f;
        o.y = (m2.y > 1.0f) ? 1.0f : 0.0f;
        o.z = (m2.z > 1.0f) ? 1.0f : 0.0f;
        o.w = (m2.w > 1.0f) ? 1.0f : 0.0f;
        *(float4*)(out + ((size_t)(b * 64 + s)) * 32000 + vb + 4 * lane) = o;
    }
}

// ---------------------------------------------------------------------------
extern "C" void kernel_launch(void* const* d_in, const int* in_sizes, int n_in,
                              void* d_out, int out_size)
{
    const int*   x     = (const int*)  d_in[0];
    const float* embed = (const float*)d_in[1];
    const float* W1    = (const float*)d_in[2];
    const float* b1    = (const float*)d_in[3];
    const float* W2    = (const float*)d_in[4];
    const float* b2    = (const float*)d_in[5];
    float* out = (float*)d_out;

    // 64 KB dynamic smem for the weight tile (idempotent host call, capture-safe)
    cudaFuncSetAttribute(snn_seq_kernel,
                         cudaFuncAttributeMaxDynamicSharedMemorySize, 65536);

    snn_masks_kernel<<<4, 1024>>>(x, embed, W1, b1);
    snn_seq_kernel<<<250, 1024, 65536>>>(W2, b2, out);
}

// round 9
// speedup vs baseline: 2.9598x; 1.0659x over previous
#include <cuda_runtime.h>
#include <cstdint>

// DialogueSNN: B=32, S=64, V=32000, E=64, H=128, T=20, beta=0.95, thr=1.0
//
// Phase 1  (snn_masks_kernel): all 1280 spike masks from the m1 recurrence.
//          Proven bit-exact vs reference (rel_err=0 across R5-R8).
// Phase 1b (snn_lists_kernel): unpack each (b,step) mask into an ascending
//          byte list of active h's, padded to a multiple of 4 with sentinel
//          h=128 (points at an all-zero smem row; c += 0.0f is bit-exact
//          since c can never be -0.0 under round-to-nearest).
// Phase 2  (snn_seq_kernel): per-(b,v) m2 recurrence; cur2 = one fp32
//          rounding per active h, ascending order (bit-exact vs reference).
//          Counted loop over the index list -> independent LDS.128 issues
//          (no serial FFS chain). Warp = (one b, 128 v), 4 v/thread.

#define BETA 0.95f

// masks[step][b][word], step = s*20+t, 4 x u32 words per (step,b)
__device__ unsigned g_masks[1280 * 32 * 4];
// packed ascending h-lists: 32 u32 words (= up to 128 bytes) per (step,b)
__device__ unsigned g_lists[1280 * 32 * 32];
// number of valid u32 words per (step,b) (count padded to multiple of 4)
__device__ int g_nw[1280 * 32];

// ---------------------------------------------------------------------------
// Kernel 1: spike-mask generation (m1 path) — UNCHANGED (bit-exact proven)
// ---------------------------------------------------------------------------
__global__ void __launch_bounds__(1024)
snn_masks_kernel(const int* __restrict__ x,
                 const float* __restrict__ embed,
                 const float* __restrict__ W1,
                 const float* __restrict__ b1)
{
    __shared__ float W1s[128 * 64];   // 32 KB
    __shared__ float embs[8 * 64];    // 2 KB

    const int tid = threadIdx.x;
    for (int i = tid; i < 128 * 64; i += 1024) W1s[i] = W1[i];

    const int b_local = tid >> 7;          // 0..7
    const int h       = tid & 127;         // 0..127
    const int b       = blockIdx.x * 8 + b_local;
    const float b1v   = b1[h];
    __syncthreads();

    float m1 = 0.0f;
    for (int s = 0; s < 64; ++s) {
        if (tid < 512) {
            int bl = tid >> 6, e = tid & 63;
            int tok = x[(blockIdx.x * 8 + bl) * 64 + s];
            embs[bl * 64 + e] = embed[(size_t)tok * 64 + e];
        }
        __syncthreads();

        float acc = 0.0f;
        #pragma unroll
        for (int e = 0; e < 64; ++e)
            acc = fmaf(embs[b_local * 64 + e], W1s[h * 64 + e], acc);
        const float cur1 = acc + b1v;

        #pragma unroll 1
        for (int t = 0; t < 20; ++t) {
            const float r = (m1 > 1.0f) ? 1.0f : 0.0f;   // reset from pre-update m1
            m1 = fmaf(BETA, m1, cur1) - r;
            const unsigned bal = __ballot_sync(0xffffffffu, m1 > 1.0f);
            if ((tid & 31) == 0)
                g_masks[((((s * 20 + t) * 32) + b) << 2) + (h >> 5)] = bal;
        }
        __syncthreads();
    }
}

// ---------------------------------------------------------------------------
// Kernel 1b: mask -> ascending h-index byte list, padded to 4 with h=128.
// One thread per (step,b): 40960 threads.
// ---------------------------------------------------------------------------
__global__ void __launch_bounds__(256)
snn_lists_kernel()
{
    const int idx = blockIdx.x * 256 + threadIdx.x;   // = step*32 + b
    if (idx >= 1280 * 32) return;

    const uint4 mk = *((const uint4*)g_masks + idx);
    unsigned char bytes[128];
    int n = 0;
    unsigned m;
    m = mk.x; while (m) { int h = __ffs(m) - 1; m &= m - 1u; bytes[n++] = (unsigned char)h; }
    m = mk.y; while (m) { int h = __ffs(m) - 1; m &= m - 1u; bytes[n++] = (unsigned char)(h + 32); }
    m = mk.z; while (m) { int h = __ffs(m) - 1; m &= m - 1u; bytes[n++] = (unsigned char)(h + 64); }
    m = mk.w; while (m) { int h = __ffs(m) - 1; m &= m - 1u; bytes[n++] = (unsigned char)(h + 96); }
    while (n & 3) bytes[n++] = 128;   // sentinel -> zero row (exact no-op add)

    const int nw = n >> 2;
    unsigned* dst = g_lists + idx * 32;
    for (int i = 0; i < nw; ++i) {
        dst[i] = (unsigned)bytes[4*i]
               | ((unsigned)bytes[4*i+1] << 8)
               | ((unsigned)bytes[4*i+2] << 16)
               | ((unsigned)bytes[4*i+3] << 24);
    }
    g_nw[idx] = nw;
}

// ---------------------------------------------------------------------------
// Kernel 2: m2 recurrence, bit-exact, 4 v/thread, list-driven.
// grid = 250 v-tiles, block = 1024 thr = 32 warps = all 32 b.
// Dynamic smem: W2Ts[129][128] floats (row 128 = zeros) = 66048 B.
// Per active h: one conflict-free LDS.128 (h warp-uniform).
// ---------------------------------------------------------------------------
extern __shared__ float W2Ts[];   // 129*128 floats

__global__ void __launch_bounds__(1024, 2)
snn_seq_kernel(const float* __restrict__ W2,
               const float* __restrict__ b2,
               float* __restrict__ out)
{
    const int tid  = threadIdx.x;
    const int lane = tid & 31;
    const int b    = tid >> 5;               // warp id == batch index 0..31
    const int vb   = blockIdx.x * 128;

    // Transpose-load the 128-row W2 tile (coalesced GMEM reads).
    for (int i = tid; i < 128 * 128; i += 1024) {
        const int v_l = i >> 7;        // 0..127
        const int h   = i & 127;       // 0..127
        W2Ts[h * 128 + v_l] = W2[(size_t)(vb + v_l) * 128 + h];
    }
    if (tid < 128) W2Ts[128 * 128 + tid] = 0.0f;   // sentinel zero row
    __syncthreads();

    const float4 bias = *(const float4*)(b2 + vb + 4 * lane);

    // this lane's float4 column base; row h is at p0[h<<5]
    const float4* p0 = (const float4*)W2Ts + lane;

    float4 m2 = make_float4(0.0f, 0.0f, 0.0f, 0.0f);

    #pragma unroll 1
    for (int s = 0; s < 64; ++s) {
        #pragma unroll 1
        for (int t = 0; t < 20; ++t) {
            const int step = s * 20 + t;
            const int idx  = step * 32 + b;
            const int nw   = __ldg(&g_nw[idx]);
            const unsigned* lp = g_lists + idx * 32;

            // ascending h, one rounding per active h per v — bit-exact.
            float4 c = make_float4(0.0f, 0.0f, 0.0f, 0.0f);
            #pragma unroll 2
            for (int i = 0; i < nw; ++i) {
                const unsigned wd = __ldg(lp + i);
                const int h0 =  wd         & 255;
                const int h1 = (wd >> 8)   & 255;
                const int h2 = (wd >> 16)  & 255;
                const int h3 =  wd >> 24;
                const float4 e0 = p0[h0 << 5];
                const float4 e1 = p0[h1 << 5];
                const float4 e2 = p0[h2 << 5];
                const float4 e3 = p0[h3 << 5];
                c.x += e0.x; c.y += e0.y; c.z += e0.z; c.w += e0.w;
                c.x += e1.x; c.y += e1.y; c.z += e1.z; c.w += e1.w;
                c.x += e2.x; c.y += e2.y; c.z += e2.z; c.w += e2.w;
                c.x += e3.x; c.y += e3.y; c.z += e3.z; c.w += e3.w;
            }

            // bias after the dot (matches reference GEMM+bias order)
            const float cx = c.x + bias.x, cy = c.y + bias.y;
            const float cz = c.z + bias.z, cw = c.w + bias.w;

            // m2 update: reset from pre-update m2, then leaky integrate
            const float rx = (m2.x > 1.0f) ? 1.0f : 0.0f;
            const float ry = (m2.y > 1.0f) ? 1.0f : 0.0f;
            const float rz = (m2.z > 1.0f) ? 1.0f : 0.0f;
            const float rw = (m2.w > 1.0f) ? 1.0f : 0.0f;
            m2.x = fmaf(BETA, m2.x, cx) - rx;
            m2.y = fmaf(BETA, m2.y, cy) - ry;
            m2.z = fmaf(BETA, m2.z, cz) - rz;
            m2.w = fmaf(BETA, m2.w, cw) - rw;
        }
        // emit spk2 for this token (coalesced 512B/warp, 16B-aligned)
        float4 o;
        o.x = (m2.x > 1.0f) ? 1.0f : 0.0f;
        o.y = (m2.y > 1.0f) ? 1.0f : 0.0f;
        o.z = (m2.z > 1.0f) ? 1.0f : 0.0f;
        o.w = (m2.w > 1.0f) ? 1.0f : 0.0f;
        *(float4*)(out + ((size_t)(b * 64 + s)) * 32000 + vb + 4 * lane) = o;
    }
}

// ---------------------------------------------------------------------------
extern "C" void kernel_launch(void* const* d_in, const int* in_sizes, int n_in,
                              void* d_out, int out_size)
{
    const int*   x     = (const int*)  d_in[0];
    const float* embed = (const float*)d_in[1];
    const float* W1    = (const float*)d_in[2];
    const float* b1    = (const float*)d_in[3];
    const float* W2    = (const float*)d_in[4];
    const float* b2    = (const float*)d_in[5];
    float* out = (float*)d_out;

    // 66 KB dynamic smem (128 weight rows + 1 zero row); capture-safe host call
    cudaFuncSetAttribute(snn_seq_kernel,
                         cudaFuncAttributeMaxDynamicSharedMemorySize, 66048);

    snn_masks_kernel<<<4, 1024>>>(x, embed, W1, b1);
    snn_lists_kernel<<<160, 256>>>();
    snn_seq_kernel<<<250, 1024, 66048>>>(W2, b2, out);
}

// round 12
// speedup vs baseline: 3.2686x; 1.1043x over previous
#include <cuda_runtime.h>
#include <cstdint>

// DialogueSNN: B=32, S=64, V=32000, E=64, H=128, T=20, beta=0.95, thr=1.0
//
// Phase 0 (snn_cur1_kernel): cur1[s][b][h] = fc1(emb) + b1, all tokens in
//          parallel. Ascending-e fmaf chain — bit-identical to prior rounds.
// Phase 1 (snn_rec_kernel):  1280-step m1 recurrence per (b,h) chain, cur1
//          prefetched per token; ballot -> g_masks. Pure latency chain.
// Phase 1b (snn_lists_kernel): mask -> ascending h byte list, padded to 4
//          with sentinel h=128 (zero smem row; +0.0f adds are exact no-ops).
// Phase 2 (snn_seq_kernel): per-(b,v) m2 recurrence; cur2 = one fp32
//          rounding per active h, ascending order (bit-exact, rel_err=0
//          across R5-R9). List-driven independent LDS.128, 4 v/thread.

#define BETA 0.95f

__device__ float    g_cur1[64 * 32 * 128];     // 1 MB
__device__ unsigned g_masks[1280 * 32 * 4];
__device__ unsigned g_lists[1280 * 32 * 32];
__device__ int      g_nw[1280 * 32];

// ---------------------------------------------------------------------------
// Kernel 0: cur1 precompute. grid = 64 (s), block = 1024 (8 b x 128 h), 4 passes.
// ---------------------------------------------------------------------------
__global__ void __launch_bounds__(1024)
snn_cur1_kernel(const int* __restrict__ x,
                const float* __restrict__ embed,
                const float* __restrict__ W1,
                const float* __restrict__ b1)
{
    __shared__ float W1s[128 * 64];   // 32 KB
    __shared__ float embs[32 * 64];   // 8 KB

    const int s   = blockIdx.x;
    const int tid = threadIdx.x;

    for (int i = tid; i < 128 * 64; i += 1024) W1s[i] = W1[i];
    for (int i = tid; i < 32 * 64; i += 1024) {
        const int b = i >> 6, e = i & 63;
        const int tok = x[b * 64 + s];
        embs[i] = embed[(size_t)tok * 64 + e];
    }
    __syncthreads();

    const int h  = tid & 127;
    const int bg = tid >> 7;          // 0..7
    const float b1v = b1[h];

    #pragma unroll
    for (int p = 0; p < 4; ++p) {
        const int b = p * 8 + bg;
        float acc = 0.0f;
        #pragma unroll
        for (int e = 0; e < 64; ++e)
            acc = fmaf(embs[b * 64 + e], W1s[h * 64 + e], acc);
        g_cur1[(s * 32 + b) * 128 + h] = acc + b1v;
    }
}

// ---------------------------------------------------------------------------
// Kernel 1: m1 recurrence -> masks. grid = 32 (b), block = 128 (h).
// Warp = 32 consecutive h -> ballot gives one mask word directly.
// ---------------------------------------------------------------------------
__global__ void __launch_bounds__(128)
snn_rec_kernel()
{
    const int b    = blockIdx.x;
    const int h    = threadIdx.x;
    const int lane = h & 31;
    const int word = h >> 5;

    float m1  = 0.0f;
    float cur = g_cur1[b * 128 + h];            // s = 0

    #pragma unroll 1
    for (int s = 0; s < 64; ++s) {
        const int sn = (s + 1 < 64) ? (s + 1) : s;
        const float nxt = g_cur1[(sn * 32 + b) * 128 + h];   // prefetch

        #pragma unroll
        for (int t = 0; t < 20; ++t) {
            const float r = (m1 > 1.0f) ? 1.0f : 0.0f;   // reset from pre-update m1
            m1 = fmaf(BETA, m1, cur) - r;
            const unsigned bal = __ballot_sync(0xffffffffu, m1 > 1.0f);
            if (lane == 0)
                g_masks[((s * 20 + t) * 32 + b) * 4 + word] = bal;
        }
        cur = nxt;
    }
}

// ---------------------------------------------------------------------------
// Kernel 1b: mask -> ascending h-index byte list, padded to 4 with h=128.
// ---------------------------------------------------------------------------
__global__ void __launch_bounds__(256)
snn_lists_kernel()
{
    const int idx = blockIdx.x * 256 + threadIdx.x;   // = step*32 + b
    if (idx >= 1280 * 32) return;

    const uint4 mk = *((const uint4*)g_masks + idx);
    unsigned char bytes[128];
    int n = 0;
    unsigned m;
    m = mk.x; while (m) { int h = __ffs(m) - 1; m &= m - 1u; bytes[n++] = (unsigned char)h; }
    m = mk.y; while (m) { int h = __ffs(m) - 1; m &= m - 1u; bytes[n++] = (unsigned char)(h + 32); }
    m = mk.z; while (m) { int h = __ffs(m) - 1; m &= m - 1u; bytes[n++] = (unsigned char)(h + 64); }
    m = mk.w; while (m) { int h = __ffs(m) - 1; m &= m - 1u; bytes[n++] = (unsigned char)(h + 96); }
    while (n & 3) bytes[n++] = 128;   // sentinel -> zero row (exact no-op add)

    const int nw = n >> 2;
    unsigned* dst = g_lists + idx * 32;
    for (int i = 0; i < nw; ++i) {
        dst[i] = (unsigned)bytes[4*i]
               | ((unsigned)bytes[4*i+1] << 8)
               | ((unsigned)bytes[4*i+2] << 16)
               | ((unsigned)bytes[4*i+3] << 24);
    }
    g_nw[idx] = nw;
}

// ---------------------------------------------------------------------------
// Kernel 2: m2 recurrence, bit-exact, 4 v/thread, list-driven. UNCHANGED (R9).
// grid = 250 v-tiles, block = 1024 thr = 32 warps = all 32 b.
// Dynamic smem: W2Ts[129][128] floats (row 128 = zeros) = 66048 B.
// ---------------------------------------------------------------------------
extern __shared__ float W2Ts[];   // 129*128 floats

__global__ void __launch_bounds__(1024, 2)
snn_seq_kernel(const float* __restrict__ W2,
               const float* __restrict__ b2,
               float* __restrict__ out)
{
    const int tid  = threadIdx.x;
    const int lane = tid & 31;
    const int b    = tid >> 5;               // warp id == batch index 0..31
    const int vb   = blockIdx.x * 128;

    for (int i = tid; i < 128 * 128; i += 1024) {
        const int v_l = i >> 7;
        const int h   = i & 127;
        W2Ts[h * 128 + v_l] = W2[(size_t)(vb + v_l) * 128 + h];
    }
    if (tid < 128) W2Ts[128 * 128 + tid] = 0.0f;   // sentinel zero row
    __syncthreads();

    const float4 bias = *(const float4*)(b2 + vb + 4 * lane);
    const float4* p0 = (const float4*)W2Ts + lane;

    float4 m2 = make_float4(0.0f, 0.0f, 0.0f, 0.0f);

    #pragma unroll 1
    for (int s = 0; s < 64; ++s) {
        #pragma unroll 1
        for (int t = 0; t < 20; ++t) {
            const int step = s * 20 + t;
            const int idx  = step * 32 + b;
            const int nw   = __ldg(&g_nw[idx]);
            const unsigned* lp = g_lists + idx * 32;

            // ascending h, one rounding per active h per v — bit-exact.
            float4 c = make_float4(0.0f, 0.0f, 0.0f, 0.0f);
            #pragma unroll 2
            for (int i = 0; i < nw; ++i) {
                const unsigned wd = __ldg(lp + i);
                const int h0 =  wd         & 255;
                const int h1 = (wd >> 8)   & 255;
                const int h2 = (wd >> 16)  & 255;
                const int h3 =  wd >> 24;
                const float4 e0 = p0[h0 << 5];
                const float4 e1 = p0[h1 << 5];
                const float4 e2 = p0[h2 << 5];
                const float4 e3 = p0[h3 << 5];
                c.x += e0.x; c.y += e0.y; c.z += e0.z; c.w += e0.w;
                c.x += e1.x; c.y += e1.y; c.z += e1.z; c.w += e1.w;
                c.x += e2.x; c.y += e2.y; c.z += e2.z; c.w += e2.w;
                c.x += e3.x; c.y += e3.y; c.z += e3.z; c.w += e3.w;
            }

            const float cx = c.x + bias.x, cy = c.y + bias.y;
            const float cz = c.z + bias.z, cw = c.w + bias.w;

            const float rx = (m2.x > 1.0f) ? 1.0f : 0.0f;
            const float ry = (m2.y > 1.0f) ? 1.0f : 0.0f;
            const float rz = (m2.z > 1.0f) ? 1.0f : 0.0f;
            const float rw = (m2.w > 1.0f) ? 1.0f : 0.0f;
            m2.x = fmaf(BETA, m2.x, cx) - rx;
            m2.y = fmaf(BETA, m2.y, cy) - ry;
            m2.z = fmaf(BETA, m2.z, cz) - rz;
            m2.w = fmaf(BETA, m2.w, cw) - rw;
        }
        float4 o;
        o.x = (m2.x > 1.0f) ? 1.0f : 0.0f;
        o.y = (m2.y > 1.0f) ? 1.0f : 0.0f;
        o.z = (m2.z > 1.0f) ? 1.0f : 0.0f;
        o.w = (m2.w > 1.0f) ? 1.0f : 0.0f;
        *(float4*)(out + ((size_t)(b * 64 + s)) * 32000 + vb + 4 * lane) = o;
    }
}

// ---------------------------------------------------------------------------
extern "C" void kernel_launch(void* const* d_in, const int* in_sizes, int n_in,
                              void* d_out, int out_size)
{
    const int*   x     = (const int*)  d_in[0];
    const float* embed = (const float*)d_in[1];
    const float* W1    = (const float*)d_in[2];
    const float* b1    = (const float*)d_in[3];
    const float* W2    = (const float*)d_in[4];
    const float* b2    = (const float*)d_in[5];
    float* out = (float*)d_out;

    cudaFuncSetAttribute(snn_seq_kernel,
                         cudaFuncAttributeMaxDynamicSharedMemorySize, 66048);

    snn_cur1_kernel<<<64, 1024>>>(x, embed, W1, b1);
    snn_rec_kernel<<<32, 128>>>();
    snn_lists_kernel<<<160, 256>>>();
    snn_seq_kernel<<<250, 1024, 66048>>>(W2, b2, out);
}

// round 13
// speedup vs baseline: 3.5180x; 1.0763x over previous
#include <cuda_runtime.h>
#include <cstdint>

// DialogueSNN: B=32, S=64, V=32000, E=64, H=128, T=20, beta=0.95, thr=1.0
//
// Phase 0 (snn_cur1_kernel): cur1[s][b][h] = fc1(emb) + b1, all tokens in
//          parallel. Ascending-e fmaf chain — bit-identical to prior rounds.
// Phase 1 (snn_rec_kernel):  1280-step m1 recurrence per (b,h) chain.
// Phase 1b (snn_lists_kernel): mask -> ascending h byte list, padded to 4
//          with sentinel h=128 (zero smem row; +0.0f adds are exact no-ops).
// Phase 2 (snn_seq_kernel): per-(b,v) m2 recurrence; cur2 = one fp32
//          rounding per active h, ascending order (bit-exact, rel_err=0
//          R5-R12). List-driven LDS.128, 4 v/thread.
//          R13: CTA = 8 warps (8 b's) x 128-v tile -> 1000 CTAs, 3 CTA/SM.
//          ceil(1000/148)=7 quarter-units/SM vs 6.76 ideal (3.6% waste)
//          replaces ceil(250/148)=2 full tiles vs 1.69 (18% waste).

#define BETA 0.95f

__device__ float    g_cur1[64 * 32 * 128];     // 1 MB
__device__ unsigned g_masks[1280 * 32 * 4];
__device__ unsigned g_lists[1280 * 32 * 32];
__device__ int      g_nw[1280 * 32];

// ---------------------------------------------------------------------------
// Kernel 0: cur1 precompute. grid = 64 (s), block = 1024 (8 b x 128 h), 4 passes.
// ---------------------------------------------------------------------------
__global__ void __launch_bounds__(1024)
snn_cur1_kernel(const int* __restrict__ x,
                const float* __restrict__ embed,
                const float* __restrict__ W1,
                const float* __restrict__ b1)
{
    __shared__ float W1s[128 * 64];   // 32 KB
    __shared__ float embs[32 * 64];   // 8 KB

    const int s   = blockIdx.x;
    const int tid = threadIdx.x;

    for (int i = tid; i < 128 * 64; i += 1024) W1s[i] = W1[i];
    for (int i = tid; i < 32 * 64; i += 1024) {
        const int b = i >> 6, e = i & 63;
        const int tok = x[b * 64 + s];
        embs[i] = embed[(size_t)tok * 64 + e];
    }
    __syncthreads();

    const int h  = tid & 127;
    const int bg = tid >> 7;          // 0..7
    const float b1v = b1[h];

    #pragma unroll
    for (int p = 0; p < 4; ++p) {
        const int b = p * 8 + bg;
        float acc = 0.0f;
        #pragma unroll
        for (int e = 0; e < 64; ++e)
            acc = fmaf(embs[b * 64 + e], W1s[h * 64 + e], acc);
        g_cur1[(s * 32 + b) * 128 + h] = acc + b1v;
    }
}

// ---------------------------------------------------------------------------
// Kernel 1: m1 recurrence -> masks. grid = 32 (b), block = 128 (h).
// ---------------------------------------------------------------------------
__global__ void __launch_bounds__(128)
snn_rec_kernel()
{
    const int b    = blockIdx.x;
    const int h    = threadIdx.x;
    const int lane = h & 31;
    const int word = h >> 5;

    float m1  = 0.0f;
    float cur = g_cur1[b * 128 + h];            // s = 0

    #pragma unroll 1
    for (int s = 0; s < 64; ++s) {
        const int sn = (s + 1 < 64) ? (s + 1) : s;
        const float nxt = g_cur1[(sn * 32 + b) * 128 + h];   // prefetch

        #pragma unroll
        for (int t = 0; t < 20; ++t) {
            const float r = (m1 > 1.0f) ? 1.0f : 0.0f;   // reset from pre-update m1
            m1 = fmaf(BETA, m1, cur) - r;
            const unsigned bal = __ballot_sync(0xffffffffu, m1 > 1.0f);
            if (lane == 0)
                g_masks[((s * 20 + t) * 32 + b) * 4 + word] = bal;
        }
        cur = nxt;
    }
}

// ---------------------------------------------------------------------------
// Kernel 1b: mask -> ascending h-index byte list, padded to 4 with h=128.
// ---------------------------------------------------------------------------
__global__ void __launch_bounds__(256)
snn_lists_kernel()
{
    const int idx = blockIdx.x * 256 + threadIdx.x;   // = step*32 + b
    if (idx >= 1280 * 32) return;

    const uint4 mk = *((const uint4*)g_masks + idx);
    unsigned char bytes[128];
    int n = 0;
    unsigned m;
    m = mk.x; while (m) { int h = __ffs(m) - 1; m &= m - 1u; bytes[n++] = (unsigned char)h; }
    m = mk.y; while (m) { int h = __ffs(m) - 1; m &= m - 1u; bytes[n++] = (unsigned char)(h + 32); }
    m = mk.z; while (m) { int h = __ffs(m) - 1; m &= m - 1u; bytes[n++] = (unsigned char)(h + 64); }
    m = mk.w; while (m) { int h = __ffs(m) - 1; m &= m - 1u; bytes[n++] = (unsigned char)(h + 96); }
    while (n & 3) bytes[n++] = 128;   // sentinel -> zero row (exact no-op add)

    const int nw = n >> 2;
    unsigned* dst = g_lists + idx * 32;
    for (int i = 0; i < nw; ++i) {
        dst[i] = (unsigned)bytes[4*i]
               | ((unsigned)bytes[4*i+1] << 8)
               | ((unsigned)bytes[4*i+2] << 16)
               | ((unsigned)bytes[4*i+3] << 24);
    }
    g_nw[idx] = nw;
}

// ---------------------------------------------------------------------------
// Kernel 2: m2 recurrence, bit-exact, 4 v/thread, list-driven.
// grid = (250 v-tiles, 4 b-groups), block = 256 thr = 8 warps.
// Warp w handles b = blockIdx.y*8 + w over v = vb + 4*lane .. +3.
// Dynamic smem: W2Ts[129][128] floats (row 128 = zeros) = 66048 B, 3 CTA/SM.
// ---------------------------------------------------------------------------
extern __shared__ float W2Ts[];   // 129*128 floats

__global__ void __launch_bounds__(256, 3)
snn_seq_kernel(const float* __restrict__ W2,
               const float* __restrict__ b2,
               float* __restrict__ out)
{
    const int tid  = threadIdx.x;
    const int lane = tid & 31;
    const int b    = blockIdx.y * 8 + (tid >> 5);
    const int vb   = blockIdx.x * 128;

    // Transpose-load the 128-row W2 tile (coalesced GMEM reads).
    for (int i = tid; i < 128 * 128; i += 256) {
        const int v_l = i >> 7;
        const int h   = i & 127;
        W2Ts[h * 128 + v_l] = W2[(size_t)(vb + v_l) * 128 + h];
    }
    if (tid < 128) W2Ts[128 * 128 + tid] = 0.0f;   // sentinel zero row
    __syncthreads();

    const float4 bias = *(const float4*)(b2 + vb + 4 * lane);
    const float4* p0 = (const float4*)W2Ts + lane;

    float4 m2 = make_float4(0.0f, 0.0f, 0.0f, 0.0f);

    #pragma unroll 1
    for (int s = 0; s < 64; ++s) {
        #pragma unroll 1
        for (int t = 0; t < 20; ++t) {
            const int step = s * 20 + t;
            const int idx  = step * 32 + b;
            const int nw   = __ldg(&g_nw[idx]);
            const unsigned* lp = g_lists + idx * 32;

            // ascending h, one rounding per active h per v — bit-exact.
            float4 c = make_float4(0.0f, 0.0f, 0.0f, 0.0f);
            #pragma unroll 2
            for (int i = 0; i < nw; ++i) {
                const unsigned wd = __ldg(lp + i);
                const int h0 =  wd         & 255;
                const int h1 = (wd >> 8)   & 255;
                const int h2 = (wd >> 16)  & 255;
                const int h3 =  wd >> 24;
                const float4 e0 = p0[h0 << 5];
                const float4 e1 = p0[h1 << 5];
                const float4 e2 = p0[h2 << 5];
                const float4 e3 = p0[h3 << 5];
                c.x += e0.x; c.y += e0.y; c.z += e0.z; c.w += e0.w;
                c.x += e1.x; c.y += e1.y; c.z += e1.z; c.w += e1.w;
                c.x += e2.x; c.y += e2.y; c.z += e2.z; c.w += e2.w;
                c.x += e3.x; c.y += e3.y; c.z += e3.z; c.w += e3.w;
            }

            const float cx = c.x + bias.x, cy = c.y + bias.y;
            const float cz = c.z + bias.z, cw = c.w + bias.w;

            const float rx = (m2.x > 1.0f) ? 1.0f : 0.0f;
            const float ry = (m2.y > 1.0f) ? 1.0f : 0.0f;
            const float rz = (m2.z > 1.0f) ? 1.0f : 0.0f;
            const float rw = (m2.w > 1.0f) ? 1.0f : 0.0f;
            m2.x = fmaf(BETA, m2.x, cx) - rx;
            m2.y = fmaf(BETA, m2.y, cy) - ry;
            m2.z = fmaf(BETA, m2.z, cz) - rz;
            m2.w = fmaf(BETA, m2.w, cw) - rw;
        }
        float4 o;
        o.x = (m2.x > 1.0f) ? 1.0f : 0.0f;
        o.y = (m2.y > 1.0f) ? 1.0f : 0.0f;
        o.z = (m2.z > 1.0f) ? 1.0f : 0.0f;
        o.w = (m2.w > 1.0f) ? 1.0f : 0.0f;
        *(float4*)(out + ((size_t)(b * 64 + s)) * 32000 + vb + 4 * lane) = o;
    }
}

// ---------------------------------------------------------------------------
extern "C" void kernel_launch(void* const* d_in, const int* in_sizes, int n_in,
                              void* d_out, int out_size)
{
    const int*   x     = (const int*)  d_in[0];
    const float* embed = (const float*)d_in[1];
    const float* W1    = (const float*)d_in[2];
    const float* b1    = (const float*)d_in[3];
    const float* W2    = (const float*)d_in[4];
    const float* b2    = (const float*)d_in[5];
    float* out = (float*)d_out;

    cudaFuncSetAttribute(snn_seq_kernel,
                         cudaFuncAttributeMaxDynamicSharedMemorySize, 66048);

    snn_cur1_kernel<<<64, 1024>>>(x, embed, W1, b1);
    snn_rec_kernel<<<32, 128>>>();
    snn_lists_kernel<<<160, 256>>>();
    snn_seq_kernel<<<dim3(250, 4), 256, 66048>>>(W2, b2, out);
}